// round 1
// baseline (speedup 1.0000x reference)
#include <cuda_runtime.h>

#define N_NODES 4096
#define IN_F    512
#define NHEADS  4
#define OUT_F   64
#define C_TOT   256   // NHEADS*OUT_F
#define ALPHA   0.2f

#define BI 16   // i-rows per block (aggregate)
#define TJ 64   // j-tile

// ---------------- scratch (device globals; no allocation allowed) ------------
__device__ float g_h  [N_NODES * C_TOT];   // x@W, row-major [n][h*64+f]
__device__ float g_s  [N_NODES * NHEADS];
__device__ float g_t  [N_NODES * NHEADS];
__device__ float g_Es [N_NODES * NHEADS];
__device__ float g_Eas[N_NODES * NHEADS];
__device__ float g_Et [N_NODES * NHEADS];
__device__ float g_Eat[N_NODES * NHEADS];

// ---------------- kernel 1: h = x @ W  (4096x512 @ 512x256) ------------------
__global__ __launch_bounds__(256) void gemm_xw(const float* __restrict__ x,
                                               const float* __restrict__ W) {
    __shared__ float sx[16][65];   // [k][m] (padded)
    __shared__ float sw[16][64];   // [k][n]
    int tid = threadIdx.x;
    int tx = tid & 15, ty = tid >> 4;
    int m0 = blockIdx.y * 64, n0 = blockIdx.x * 64;

    float c[4][4];
    #pragma unroll
    for (int i = 0; i < 4; i++)
        #pragma unroll
        for (int j = 0; j < 4; j++) c[i][j] = 0.f;

    for (int kk = 0; kk < IN_F; kk += 16) {
        #pragma unroll
        for (int p = 0; p < 4; p++) {
            int idx = tid + p * 256;
            int r = idx >> 4, cc = idx & 15;               // r: m-row, cc: k
            sx[cc][r] = x[(m0 + r) * IN_F + kk + cc];
        }
        #pragma unroll
        for (int p = 0; p < 4; p++) {
            int idx = tid + p * 256;
            int r = idx >> 6, cc = idx & 63;               // r: k, cc: n
            sw[r][cc] = W[(kk + r) * C_TOT + n0 + cc];
        }
        __syncthreads();
        #pragma unroll
        for (int k = 0; k < 16; k++) {
            float a0 = sx[k][ty * 4 + 0];
            float a1 = sx[k][ty * 4 + 1];
            float a2 = sx[k][ty * 4 + 2];
            float a3 = sx[k][ty * 4 + 3];
            float b0 = sw[k][tx * 4 + 0];
            float b1 = sw[k][tx * 4 + 1];
            float b2 = sw[k][tx * 4 + 2];
            float b3 = sw[k][tx * 4 + 3];
            c[0][0] += a0 * b0; c[0][1] += a0 * b1; c[0][2] += a0 * b2; c[0][3] += a0 * b3;
            c[1][0] += a1 * b0; c[1][1] += a1 * b1; c[1][2] += a1 * b2; c[1][3] += a1 * b3;
            c[2][0] += a2 * b0; c[2][1] += a2 * b1; c[2][2] += a2 * b2; c[2][3] += a2 * b3;
            c[3][0] += a3 * b0; c[3][1] += a3 * b1; c[3][2] += a3 * b2; c[3][3] += a3 * b3;
        }
        __syncthreads();
    }
    #pragma unroll
    for (int i = 0; i < 4; i++)
        #pragma unroll
        for (int j = 0; j < 4; j++)
            g_h[(m0 + ty * 4 + i) * C_TOT + n0 + tx * 4 + j] = c[i][j];
}

// ---------------- kernel 1b: s,t and factorized exp coefficients -------------
// exp(leaky(s+t)) = (s+t>0) ? exp(s)exp(t) : exp(a*s)exp(a*t)
__global__ __launch_bounds__(256) void attn_coef(const float* __restrict__ a) {
    int gt = blockIdx.x * 256 + threadIdx.x;   // 0 .. 16383 == n*4+h
    int n = gt >> 2, h = gt & 3;
    const float* hp = &g_h[n * C_TOT + h * OUT_F];
    float s = 0.f, t = 0.f;
    #pragma unroll 8
    for (int f = 0; f < OUT_F; f++) {
        float hv = hp[f];
        s += hv * a[f];
        t += hv * a[OUT_F + f];
    }
    g_s [gt] = s;                 g_t  [gt] = t;
    g_Es[gt] = expf(s);           g_Et [gt] = expf(t);
    g_Eas[gt] = expf(ALPHA * s);  g_Eat[gt] = expf(ALPHA * t);
}

// ---------------- kernel 2: masked softmax-weighted aggregation --------------
// out[i][h*64+f] = (1/l_i_h) * sum_j p(i,j,h) * g_h[j][h*64+f]
__global__ __launch_bounds__(256) void aggregate(const int* __restrict__ adj,
                                                 float* __restrict__ out) {
    __shared__ float sp[TJ * 4 * BI];    // [jj][h][i], 16KB
    __shared__ int   sadj[TJ * 17];      // [jj][i] padded
    __shared__ float stv[TJ * 4], stE[TJ * 4], stEa[TJ * 4];
    __shared__ float slred[256];
    __shared__ float slinv[64];          // [h*16+i]

    int tid = threadIdx.x;
    int i0 = blockIdx.x * BI;

    // phase-1 identity: tid = jb*64 + h*16 + i
    int p1_i  = tid & 15;
    int p1_h  = (tid >> 4) & 3;
    int p1_jb = tid >> 6;                // 0..3

    float sv   = g_s  [(i0 + p1_i) * 4 + p1_h];
    float Esv  = g_Es [(i0 + p1_i) * 4 + p1_h];
    float Easv = g_Eas[(i0 + p1_i) * 4 + p1_h];
    float lpart = 0.f;

    // phase-2 identity: tid = h*64 + f
    int p2_h = tid >> 6;

    float acc[BI];
    #pragma unroll
    for (int i = 0; i < BI; i++) acc[i] = 0.f;

    for (int j0 = 0; j0 < N_NODES; j0 += TJ) {
        __syncthreads();
        // stage adj tile (16 x 64) coalesced, transposed into [jj][i]
        #pragma unroll
        for (int p = 0; p < 4; p++) {
            int idx = tid + p * 256;
            int r  = idx >> 6;           // i (0..15)
            int cc = idx & 63;           // jj
            sadj[cc * 17 + r] = adj[(i0 + r) * N_NODES + j0 + cc];
        }
        // stage destination-side factors for this j tile (coalesced)
        stv [tid] = g_t  [j0 * 4 + tid];
        stE [tid] = g_Et [j0 * 4 + tid];
        stEa[tid] = g_Eat[j0 * 4 + tid];
        __syncthreads();

        // phase 1: unnormalized attention weights p into shared
        #pragma unroll
        for (int k = 0; k < 16; k++) {
            int jj = p1_jb + 4 * k;
            int aj = sadj[jj * 17 + p1_i];
            float p = 0.f;
            if (aj > 0) {
                float tv = stv[jj * 4 + p1_h];
                p = (sv + tv > 0.f) ? Esv  * stE [jj * 4 + p1_h]
                                    : Easv * stEa[jj * 4 + p1_h];
            }
            sp[(jj * 4 + p1_h) * 16 + p1_i] = p;
            lpart += p;
        }
        __syncthreads();

        // phase 2: acc[i] += p[jj][h][i] * h[j][h*64+f]; 16 FMAs per h-load
        const float* hbase = &g_h[j0 * C_TOT + tid];
        #pragma unroll 4
        for (int jj = 0; jj < TJ; jj++) {
            float hv = hbase[jj * C_TOT];
            const float4* pr = (const float4*)&sp[(jj * 4 + p2_h) * 16];
            float4 q0 = pr[0], q1 = pr[1], q2 = pr[2], q3 = pr[3];
            acc[0]  += q0.x * hv; acc[1]  += q0.y * hv;
            acc[2]  += q0.z * hv; acc[3]  += q0.w * hv;
            acc[4]  += q1.x * hv; acc[5]  += q1.y * hv;
            acc[6]  += q1.z * hv; acc[7]  += q1.w * hv;
            acc[8]  += q2.x * hv; acc[9]  += q2.y * hv;
            acc[10] += q2.z * hv; acc[11] += q2.w * hv;
            acc[12] += q3.x * hv; acc[13] += q3.y * hv;
            acc[14] += q3.z * hv; acc[15] += q3.w * hv;
        }
    }

    // reduce l over the 4 jb-groups (tid%64 identifies (h,i))
    slred[tid] = lpart;
    __syncthreads();
    if (tid < 64) {
        float l = slred[tid] + slred[tid + 64] + slred[tid + 128] + slred[tid + 192];
        slinv[tid] = 1.f / l;            // index = h*16 + i
    }
    __syncthreads();

    #pragma unroll
    for (int i = 0; i < BI; i++)
        out[(i0 + i) * C_TOT + tid] = acc[i] * slinv[p2_h * 16 + i];
}

// ---------------- launch ------------------------------------------------------
extern "C" void kernel_launch(void* const* d_in, const int* in_sizes, int n_in,
                              void* d_out, int out_size) {
    const float* x   = (const float*)d_in[0];
    const int*   adj = (const int*)  d_in[1];
    const float* W   = (const float*)d_in[2];
    const float* a   = (const float*)d_in[3];
    float* out = (float*)d_out;

    dim3 g1(C_TOT / 64, N_NODES / 64);
    gemm_xw<<<g1, 256>>>(x, W);
    attn_coef<<<(N_NODES * NHEADS) / 256, 256>>>(a);
    aggregate<<<N_NODES / BI, 256>>>(adj, out);
}

// round 3
// speedup vs baseline: 2.3260x; 2.3260x over previous
#include <cuda_runtime.h>
#include <cstdint>

#define N_NODES 4096
#define IN_F    512
#define NHEADS  4
#define OUT_F   64
#define C_TOT   256
#define ALPHA   0.2f

// ---------------- scratch ----------------
__device__ float    g_h   [N_NODES * C_TOT];          // x@W  [n][h*64+f]
__device__ float    g_hT  [C_TOT * N_NODES];          // [(h*64+f)][j]
__device__ float    g_s   [NHEADS * N_NODES];         // [h][n]
__device__ float    g_t   [NHEADS * N_NODES];
__device__ float    g_Es  [NHEADS * N_NODES];
__device__ float    g_Eas [NHEADS * N_NODES];
__device__ float    g_Et  [NHEADS * N_NODES];
__device__ float    g_Eat [NHEADS * N_NODES];
__device__ uint32_t g_adjbits[N_NODES * (N_NODES / 32)];  // 2MB bitmask

// ---------------- helpers ----------------
__device__ __forceinline__ uint32_t f2tf32(float f) {
    uint32_t u;
    asm("cvt.rna.tf32.f32 %0, %1;" : "=r"(u) : "f"(f));
    return u;
}
__device__ __forceinline__ void mma_tf32_16n8k8(float* d, const uint32_t* a,
                                                uint32_t b0, uint32_t b1) {
    asm volatile(
        "mma.sync.aligned.m16n8k8.row.col.f32.tf32.tf32.f32 "
        "{%0,%1,%2,%3}, {%4,%5,%6,%7}, {%8,%9}, {%0,%1,%2,%3};"
        : "+f"(d[0]), "+f"(d[1]), "+f"(d[2]), "+f"(d[3])
        : "r"(a[0]), "r"(a[1]), "r"(a[2]), "r"(a[3]), "r"(b0), "r"(b1));
}

// ---------------- kernel 1: h = x @ W (fp32 SIMT) ----------------
__global__ __launch_bounds__(256) void gemm_xw(const float* __restrict__ x,
                                               const float* __restrict__ W) {
    __shared__ float sx[16][65];
    __shared__ float sw[16][64];
    int tid = threadIdx.x;
    int tx = tid & 15, ty = tid >> 4;
    int m0 = blockIdx.y * 64, n0 = blockIdx.x * 64;
    float c[4][4];
    #pragma unroll
    for (int i = 0; i < 4; i++)
        #pragma unroll
        for (int j = 0; j < 4; j++) c[i][j] = 0.f;
    for (int kk = 0; kk < IN_F; kk += 16) {
        #pragma unroll
        for (int p = 0; p < 4; p++) {
            int idx = tid + p * 256;
            int r = idx >> 4, cc = idx & 15;
            sx[cc][r] = x[(m0 + r) * IN_F + kk + cc];
        }
        #pragma unroll
        for (int p = 0; p < 4; p++) {
            int idx = tid + p * 256;
            int r = idx >> 6, cc = idx & 63;
            sw[r][cc] = W[(kk + r) * C_TOT + n0 + cc];
        }
        __syncthreads();
        #pragma unroll
        for (int k = 0; k < 16; k++) {
            float a0 = sx[k][ty*4+0], a1 = sx[k][ty*4+1], a2 = sx[k][ty*4+2], a3 = sx[k][ty*4+3];
            float b0 = sw[k][tx*4+0], b1 = sw[k][tx*4+1], b2 = sw[k][tx*4+2], b3 = sw[k][tx*4+3];
            c[0][0]+=a0*b0; c[0][1]+=a0*b1; c[0][2]+=a0*b2; c[0][3]+=a0*b3;
            c[1][0]+=a1*b0; c[1][1]+=a1*b1; c[1][2]+=a1*b2; c[1][3]+=a1*b3;
            c[2][0]+=a2*b0; c[2][1]+=a2*b1; c[2][2]+=a2*b2; c[2][3]+=a2*b3;
            c[3][0]+=a3*b0; c[3][1]+=a3*b1; c[3][2]+=a3*b2; c[3][3]+=a3*b3;
        }
        __syncthreads();
    }
    #pragma unroll
    for (int i = 0; i < 4; i++)
        #pragma unroll
        for (int j = 0; j < 4; j++)
            g_h[(m0 + ty*4 + i) * C_TOT + n0 + tx*4 + j] = c[i][j];
}

// ---------------- kernel 1b: factorized attention coefficients --------------
// exp(leaky(s+t)) = (s+t>0) ? exp(s)exp(t) : exp(a*s)exp(a*t)
__global__ __launch_bounds__(256) void attn_coef(const float* __restrict__ a) {
    int gt = blockIdx.x * 256 + threadIdx.x;   // n*4+h
    int n = gt >> 2, h = gt & 3;
    const float* hp = &g_h[n * C_TOT + h * OUT_F];
    float s = 0.f, t = 0.f;
    #pragma unroll 8
    for (int f = 0; f < OUT_F; f++) {
        float hv = hp[f];
        s += hv * a[f];
        t += hv * a[OUT_F + f];
    }
    int o = h * N_NODES + n;
    g_s[o] = s;                 g_t[o]   = t;
    g_Es[o] = expf(s);          g_Et[o]  = expf(t);
    g_Eas[o] = expf(ALPHA * s); g_Eat[o] = expf(ALPHA * t);
}

// ---------------- kernel 1c: transpose h -> hT ----------------
__global__ __launch_bounds__(256) void transpose_h() {
    __shared__ float t[32][33];
    int jx = blockIdx.x * 32, cx = blockIdx.y * 32;
    int lx = threadIdx.x & 31, ly = threadIdx.x >> 5;
    #pragma unroll
    for (int q = 0; q < 4; q++)
        t[ly + q*8][lx] = g_h[(jx + ly + q*8) * C_TOT + cx + lx];
    __syncthreads();
    #pragma unroll
    for (int q = 0; q < 4; q++)
        g_hT[(cx + ly + q*8) * N_NODES + jx + lx] = t[lx][ly + q*8];
}

// ---------------- kernel 1d: pack adj into bits ----------------
__global__ __launch_bounds__(256) void pack_adj(const int* __restrict__ adj) {
    int g = blockIdx.x * 256 + threadIdx.x;
    int w = g >> 5, lane = g & 31;
    int v = adj[w * 32 + lane];
    uint32_t b = __ballot_sync(0xffffffffu, v > 0);
    if (lane == 0) g_adjbits[w] = b;
}

// ---------------- kernel 2: HMMA tf32 masked-softmax aggregation -------------
// dynamic smem layout (bytes)
#define OFF_TT   0u        // 4096 f  (t)
#define OFF_TE   16384u    // 4096 f  (Et)
#define OFF_TEA  32768u    // 4096 f  (Eat)
#define OFF_P    49152u    // 128 x 36 u32  (tf32 P tile)
#define OFF_B    67584u    // 64  x 36 u32  (tf32 B tile, [n][k])
#define OFF_RED  76800u    // 256 f
#define OFF_LI   77824u    // 128 f
#define SMEM_AGG 78336

__global__ __launch_bounds__(256, 1) void aggregate_mma(float* __restrict__ out) {
    extern __shared__ char smem[];
    float*    st_t  = (float*)(smem + OFF_TT);
    float*    st_e  = (float*)(smem + OFF_TE);
    float*    st_ea = (float*)(smem + OFF_TEA);
    uint32_t* sp    = (uint32_t*)(smem + OFF_P);
    uint32_t* sB    = (uint32_t*)(smem + OFF_B);
    float*    sred  = (float*)(smem + OFF_RED);
    float*    slinv = (float*)(smem + OFF_LI);

    int tid = threadIdx.x, wid = tid >> 5, lane = tid & 31;
    int h = blockIdx.x & 3, tile = blockIdx.x >> 2;
    int i0 = tile * 128;

    // preload j-side factors for ALL j (coalesced float4)
    {
        const float4* gt  = (const float4*)&g_t  [h * N_NODES];
        const float4* ge  = (const float4*)&g_Et [h * N_NODES];
        const float4* gea = (const float4*)&g_Eat[h * N_NODES];
        #pragma unroll
        for (int q = 0; q < 4; q++) {
            int idx = tid + q * 256;
            ((float4*)st_t )[idx] = gt [idx];
            ((float4*)st_e )[idx] = ge [idx];
            ((float4*)st_ea)[idx] = gea[idx];
        }
    }

    // per-thread build identity: row i, half of the 32 k's
    int i = tid >> 1, half = tid & 1;
    float sv  = g_s  [h * N_NODES + i0 + i];
    float es  = g_Es [h * N_NODES + i0 + i];
    float eas = g_Eas[h * N_NODES + i0 + i];
    const uint32_t* mrow = &g_adjbits[(i0 + i) * 128];
    float lpart = 0.f;

    // mma identities
    int wrow = wid * 16, gid = lane >> 2, tig = lane & 3;
    int p2h = h * 64;
    float acc[8][4];
    #pragma unroll
    for (int nb = 0; nb < 8; nb++)
        #pragma unroll
        for (int q = 0; q < 4; q++) acc[nb][q] = 0.f;

    // B staging identity: n = idx>>3, kseg = idx&7  (float4 of 4 consecutive k)
    int bn0 = tid >> 3, bk0 = tid & 7;
    int bn1 = (tid + 256) >> 3, bk1 = (tid + 256) & 7;
    const float* hT0 = &g_hT[(p2h + bn0) * N_NODES];
    const float* hT1 = &g_hT[(p2h + bn1) * N_NODES];

    // software pipeline: mask + B registers for chunk 0
    uint32_t mcur = mrow[0];
    float4 bv0 = *(const float4*)(hT0 + bk0 * 4);
    float4 bv1 = *(const float4*)(hT1 + bk1 * 4);

    for (int c = 0; c < 128; c++) {
        __syncthreads();   // previous chunk's MMA done reading sp/sB

        // ---- store B tile (tf32) : sB[n][k], pad 36 ----
        {
            uint4 u0 = { f2tf32(bv0.x), f2tf32(bv0.y), f2tf32(bv0.z), f2tf32(bv0.w) };
            uint4 u1 = { f2tf32(bv1.x), f2tf32(bv1.y), f2tf32(bv1.z), f2tf32(bv1.w) };
            *(uint4*)&sB[bn0 * 36 + bk0 * 4] = u0;
            *(uint4*)&sB[bn1 * 36 + bk1 * 4] = u1;
        }

        // ---- build P tile (tf32) + row-sum on the SAME tf32 values ----
        {
            uint32_t m = mcur >> (half * 16);
            int jb = c * 32 + half * 16;
            #pragma unroll
            for (int k4 = 0; k4 < 4; k4++) {
                int k = jb + k4 * 4;
                uint4 pv;
                #pragma unroll
                for (int e = 0; e < 4; e++) {
                    float tv = st_t[k + e];
                    bool pos = (sv + tv) > 0.f;
                    float p = (pos ? es : eas) * (pos ? st_e[k + e] : st_ea[k + e]);
                    p = ((m >> (k4 * 4 + e)) & 1) ? p : 0.f;
                    uint32_t pu = f2tf32(p);
                    lpart += __uint_as_float(pu);
                    (&pv.x)[e] = pu;
                }
                *(uint4*)&sp[i * 36 + half * 16 + k4 * 4] = pv;
            }
        }

        // prefetch next chunk's mask + B
        if (c < 127) {
            mcur = mrow[c + 1];
            int j0n = (c + 1) * 32;
            bv0 = *(const float4*)(hT0 + j0n + bk0 * 4);
            bv1 = *(const float4*)(hT1 + j0n + bk1 * 4);
        }
        __syncthreads();

        // ---- MMA: warp tile 16x64, K=32 ----
        #pragma unroll
        for (int kst = 0; kst < 4; kst++) {
            int k0 = kst * 8;
            uint32_t a[4];
            a[0] = sp[(wrow + gid) * 36 + k0 + tig];
            a[1] = sp[(wrow + gid + 8) * 36 + k0 + tig];
            a[2] = sp[(wrow + gid) * 36 + k0 + tig + 4];
            a[3] = sp[(wrow + gid + 8) * 36 + k0 + tig + 4];
            uint32_t b0[8], b1[8];
            #pragma unroll
            for (int nb = 0; nb < 8; nb++) {
                b0[nb] = sB[(nb * 8 + gid) * 36 + k0 + tig];
                b1[nb] = sB[(nb * 8 + gid) * 36 + k0 + tig + 4];
            }
            #pragma unroll
            for (int nb = 0; nb < 8; nb++)
                mma_tf32_16n8k8(acc[nb], a, b0[nb], b1[nb]);
        }
    }

    // ---- row-sum reduction -> 1/l ----
    __syncthreads();
    sred[tid] = lpart;
    __syncthreads();
    if (tid < 128) slinv[tid] = 1.f / (sred[tid * 2] + sred[tid * 2 + 1]);
    __syncthreads();

    // ---- epilogue: normalize + store ----
    {
        int rlo = wrow + gid, rhi = rlo + 8;
        float invlo = slinv[rlo], invhi = slinv[rhi];
        float* olo = &out[(i0 + rlo) * C_TOT + p2h + 2 * tig];
        float* ohi = &out[(i0 + rhi) * C_TOT + p2h + 2 * tig];
        #pragma unroll
        for (int nb = 0; nb < 8; nb++) {
            float2 vlo = { acc[nb][0] * invlo, acc[nb][1] * invlo };
            float2 vhi = { acc[nb][2] * invhi, acc[nb][3] * invhi };
            *(float2*)(olo + nb * 8) = vlo;
            *(float2*)(ohi + nb * 8) = vhi;
        }
    }
}

// ---------------- launch ----------------
extern "C" void kernel_launch(void* const* d_in, const int* in_sizes, int n_in,
                              void* d_out, int out_size) {
    const float* x   = (const float*)d_in[0];
    const int*   adj = (const int*)  d_in[1];
    const float* W   = (const float*)d_in[2];
    const float* a   = (const float*)d_in[3];
    float* out = (float*)d_out;

    cudaFuncSetAttribute(aggregate_mma,
                         cudaFuncAttributeMaxDynamicSharedMemorySize, SMEM_AGG);

    pack_adj<<<(N_NODES * N_NODES) / 256, 256>>>(adj);
    dim3 g1(C_TOT / 64, N_NODES / 64);
    gemm_xw<<<g1, 256>>>(x, W);
    attn_coef<<<(N_NODES * NHEADS) / 256, 256>>>(a);
    dim3 g2(N_NODES / 32, C_TOT / 32);
    transpose_h<<<g2, 256>>>();
    aggregate_mma<<<(N_NODES / 128) * NHEADS, 256, SMEM_AGG>>>(out);
}

// round 4
// speedup vs baseline: 2.7132x; 1.1665x over previous
#include <cuda_runtime.h>
#include <cuda_fp16.h>
#include <cstdint>

#define N_NODES 4096
#define IN_F    512
#define NHEADS  4
#define OUT_F   64
#define C_TOT   256
#define ALPHA   0.2f
#define ESHIFT  2.0f

// ---------------- scratch ----------------
__device__ float    g_h   [N_NODES * C_TOT];          // x@W  [n][h*64+f]  (fp32)
__device__ __half   g_hT  [C_TOT * N_NODES];          // [(h*64+f)][j]     (fp16)
__device__ float    g_WT  [C_TOT * IN_F];             // W transposed [n][k]
__device__ float    g_s   [NHEADS * N_NODES];
__device__ float    g_Es  [NHEADS * N_NODES];         // exp(s-2)
__device__ float    g_Eas [NHEADS * N_NODES];         // exp(a*s-2)
__device__ float    g_t   [NHEADS * N_NODES];
__device__ float    g_Et  [NHEADS * N_NODES];         // exp(t-2)
__device__ float    g_Eat [NHEADS * N_NODES];         // exp(a*t-2)
__device__ uint32_t g_adjbits[N_NODES * (N_NODES / 32)];

// ---------------- helpers ----------------
__device__ __forceinline__ uint32_t f2tf32(float f) {
    uint32_t u;
    asm("cvt.rna.tf32.f32 %0, %1;" : "=r"(u) : "f"(f));
    return u;
}
__device__ __forceinline__ void mma_tf32_16n8k8(float* d, const uint32_t* a,
                                                uint32_t b0, uint32_t b1) {
    asm volatile(
        "mma.sync.aligned.m16n8k8.row.col.f32.tf32.tf32.f32 "
        "{%0,%1,%2,%3}, {%4,%5,%6,%7}, {%8,%9}, {%0,%1,%2,%3};"
        : "+f"(d[0]), "+f"(d[1]), "+f"(d[2]), "+f"(d[3])
        : "r"(a[0]), "r"(a[1]), "r"(a[2]), "r"(a[3]), "r"(b0), "r"(b1));
}
__device__ __forceinline__ void mma_f16_16n8k16(float* d, const uint32_t* a,
                                                uint32_t b0, uint32_t b1) {
    asm volatile(
        "mma.sync.aligned.m16n8k16.row.col.f32.f16.f16.f32 "
        "{%0,%1,%2,%3}, {%4,%5,%6,%7}, {%8,%9}, {%0,%1,%2,%3};"
        : "+f"(d[0]), "+f"(d[1]), "+f"(d[2]), "+f"(d[3])
        : "r"(a[0]), "r"(a[1]), "r"(a[2]), "r"(a[3]), "r"(b0), "r"(b1));
}

// ---------------- kernel 0: transpose W -> g_WT ----------------
__global__ __launch_bounds__(256) void transpose_w(const float* __restrict__ W) {
    __shared__ float t[32][33];
    int kx = blockIdx.x * 32, nx = blockIdx.y * 32;
    int lx = threadIdx.x & 31, ly = threadIdx.x >> 5;
    #pragma unroll
    for (int q = 0; q < 4; q++)
        t[ly + q*8][lx] = W[(kx + ly + q*8) * C_TOT + nx + lx];
    __syncthreads();
    #pragma unroll
    for (int q = 0; q < 4; q++)
        g_WT[(nx + ly + q*8) * IN_F + kx + lx] = t[lx][ly + q*8];
}

// ---------------- kernel 1: h = x @ W via tf32 HMMA ----------------
// tiles: 128 (m) x 64 (n), K-loop 16 x 32
__global__ __launch_bounds__(256) void gemm_xw_mma(const float* __restrict__ x) {
    __shared__ uint32_t sA[128 * 36];
    __shared__ uint32_t sB[64 * 36];

    int tid = threadIdx.x, wid = tid >> 5, lane = tid & 31;
    int gid = lane >> 2, tig = lane & 3;
    int wrow = wid * 16;
    int n0 = blockIdx.x * 64, m0 = blockIdx.y * 128;

    float acc[8][4];
    #pragma unroll
    for (int nb = 0; nb < 8; nb++)
        #pragma unroll
        for (int q = 0; q < 4; q++) acc[nb][q] = 0.f;

    // staging identities
    int ar = tid >> 1, aks = (tid & 1) * 16;          // A: 128 rows x 32 k
    int bn = tid >> 2, bks = (tid & 3) * 8;           // B: 64 rows x 32 k
    const float* aptr = &x[(m0 + ar) * IN_F + aks];
    const float* bptr = &g_WT[(n0 + bn) * IN_F + bks];

    float4 av[4], bv[2];
    #pragma unroll
    for (int e = 0; e < 4; e++) av[e] = *(const float4*)(aptr + 4 * e);
    #pragma unroll
    for (int e = 0; e < 2; e++) bv[e] = *(const float4*)(bptr + 4 * e);

    for (int it = 0; it < 16; it++) {
        __syncthreads();
        #pragma unroll
        for (int e = 0; e < 4; e++) {
            uint4 u = { f2tf32(av[e].x), f2tf32(av[e].y), f2tf32(av[e].z), f2tf32(av[e].w) };
            *(uint4*)&sA[ar * 36 + aks + 4 * e] = u;
        }
        #pragma unroll
        for (int e = 0; e < 2; e++) {
            uint4 u = { f2tf32(bv[e].x), f2tf32(bv[e].y), f2tf32(bv[e].z), f2tf32(bv[e].w) };
            *(uint4*)&sB[bn * 36 + bks + 4 * e] = u;
        }
        if (it < 15) {
            int kk = (it + 1) * 32;
            #pragma unroll
            for (int e = 0; e < 4; e++) av[e] = *(const float4*)(aptr + kk + 4 * e);
            #pragma unroll
            for (int e = 0; e < 2; e++) bv[e] = *(const float4*)(bptr + kk + 4 * e);
        }
        __syncthreads();

        #pragma unroll
        for (int kst = 0; kst < 4; kst++) {
            int k0 = kst * 8;
            uint32_t a[4];
            a[0] = sA[(wrow + gid)     * 36 + k0 + tig];
            a[1] = sA[(wrow + gid + 8) * 36 + k0 + tig];
            a[2] = sA[(wrow + gid)     * 36 + k0 + tig + 4];
            a[3] = sA[(wrow + gid + 8) * 36 + k0 + tig + 4];
            #pragma unroll
            for (int nb = 0; nb < 8; nb++) {
                uint32_t b0 = sB[(nb * 8 + gid) * 36 + k0 + tig];
                uint32_t b1 = sB[(nb * 8 + gid) * 36 + k0 + tig + 4];
                mma_tf32_16n8k8(acc[nb], a, b0, b1);
            }
        }
    }

    // epilogue
    {
        int rlo = m0 + wrow + gid, rhi = rlo + 8;
        #pragma unroll
        for (int nb = 0; nb < 8; nb++) {
            int cb = n0 + nb * 8 + 2 * tig;
            *(float2*)&g_h[rlo * C_TOT + cb] = make_float2(acc[nb][0], acc[nb][1]);
            *(float2*)&g_h[rhi * C_TOT + cb] = make_float2(acc[nb][2], acc[nb][3]);
        }
    }
}

// ---------------- kernel 1b: factorized attention coefficients --------------
__global__ __launch_bounds__(256) void attn_coef(const float* __restrict__ a) {
    int gt = blockIdx.x * 256 + threadIdx.x;   // n*4+h
    int n = gt >> 2, h = gt & 3;
    const float* hp = &g_h[n * C_TOT + h * OUT_F];
    float s = 0.f, t = 0.f;
    #pragma unroll 8
    for (int f = 0; f < OUT_F; f++) {
        float hv = hp[f];
        s += hv * a[f];
        t += hv * a[OUT_F + f];
    }
    int o = h * N_NODES + n;
    g_s[o]  = s;                          g_t[o]   = t;
    g_Es[o] = expf(s - ESHIFT);           g_Et[o]  = expf(t - ESHIFT);
    g_Eas[o] = expf(ALPHA * s - ESHIFT);  g_Eat[o] = expf(ALPHA * t - ESHIFT);
}

// ---------------- kernel 1c: transpose h -> hT (fp16) ----------------
__global__ __launch_bounds__(256) void transpose_h() {
    __shared__ float t[32][33];
    int jx = blockIdx.x * 32, cx = blockIdx.y * 32;
    int lx = threadIdx.x & 31, ly = threadIdx.x >> 5;
    #pragma unroll
    for (int q = 0; q < 4; q++)
        t[ly + q*8][lx] = g_h[(jx + ly + q*8) * C_TOT + cx + lx];
    __syncthreads();
    #pragma unroll
    for (int q = 0; q < 4; q++)
        g_hT[(cx + ly + q*8) * N_NODES + jx + lx] = __float2half(t[lx][ly + q*8]);
}

// ---------------- kernel 1d: pack adj into bits ----------------
__global__ __launch_bounds__(256) void pack_adj(const int* __restrict__ adj) {
    int g = blockIdx.x * 256 + threadIdx.x;
    int w = g >> 5, lane = g & 31;
    int v = adj[w * 32 + lane];
    uint32_t b = __ballot_sync(0xffffffffu, v > 0);
    if (lane == 0) g_adjbits[w] = b;
}

// ---------------- kernel 2: fp16 HMMA masked-softmax aggregation -------------
// dynamic smem (bytes)
#define OFF_TT   0u        // 4096 f
#define OFF_TE   16384u
#define OFF_TEA  32768u
#define OFF_P    49152u    // 128 x 40 halves = 10240
#define OFF_B    59392u    // 64 x 40 halves  = 5120
#define OFF_RED  64512u    // 512 f
#define OFF_LI   66560u    // 128 f
#define SMEM_AGG 67072

__global__ __launch_bounds__(512, 1) void aggregate_mma(float* __restrict__ out) {
    extern __shared__ char smem[];
    float*  st_t  = (float*)(smem + OFF_TT);
    float*  st_e  = (float*)(smem + OFF_TE);
    float*  st_ea = (float*)(smem + OFF_TEA);
    __half* sPh   = (__half*)(smem + OFF_P);
    __half* sBh   = (__half*)(smem + OFF_B);
    float*  sred  = (float*)(smem + OFF_RED);
    float*  slinv = (float*)(smem + OFF_LI);

    int tid = threadIdx.x, wid = tid >> 5, lane = tid & 31;
    int gid = lane >> 2, tig = lane & 3;
    int h = blockIdx.x & 3, tile = blockIdx.x >> 2;
    int i0 = tile * 128;
    int p2h = h * 64;

    // preload j-side factors for ALL j
    {
        const float4* gt  = (const float4*)&g_t  [h * N_NODES];
        const float4* ge  = (const float4*)&g_Et [h * N_NODES];
        const float4* gea = (const float4*)&g_Eat[h * N_NODES];
        #pragma unroll
        for (int q = 0; q < 2; q++) {
            int idx = tid + q * 512;
            ((float4*)st_t )[idx] = gt [idx];
            ((float4*)st_e )[idx] = ge [idx];
            ((float4*)st_ea)[idx] = gea[idx];
        }
    }

    // build identity: row i, quarter q (8 k's)
    int i = tid >> 2, q = tid & 3;
    float sv  = g_s  [h * N_NODES + i0 + i];
    float es  = g_Es [h * N_NODES + i0 + i];
    float eas = g_Eas[h * N_NODES + i0 + i];
    const uint32_t* mrow = &g_adjbits[(i0 + i) * 128];
    float lpart = 0.f;

    // mma identity: 16 warps -> 8 row-blocks x 2 col-halves
    int wrow = (wid >> 1) * 16, cc = wid & 1;
    float acc[4][4];
    #pragma unroll
    for (int nb = 0; nb < 4; nb++)
        #pragma unroll
        for (int e = 0; e < 4; e++) acc[nb][e] = 0.f;

    // B staging: n = tid>>3 (0..63), 4 halves at k = (tid&7)*4
    int bn = tid >> 3, bk = (tid & 7) * 4;
    const __half* hTrow = &g_hT[(p2h + bn) * N_NODES];

    uint32_t mcur = mrow[0];
    uint2 bv = *(const uint2*)(hTrow + bk);

    for (int c = 0; c < 128; c++) {
        __syncthreads();
        // ---- stage B ----
        *(uint2*)&sBh[bn * 40 + bk] = bv;
        // ---- build P (fp16) + exact row-sum of rounded values ----
        {
            uint32_t m8 = (mcur >> (q * 8)) & 0xffu;
            int kg = c * 32 + q * 8;
            uint32_t pk[4];
            #pragma unroll
            for (int e2 = 0; e2 < 4; e2++) {
                uint32_t w = 0;
                #pragma unroll
                for (int sub = 0; sub < 2; sub++) {
                    int e = e2 * 2 + sub;
                    float tv = st_t[kg + e];
                    bool pos = (sv + tv) > 0.f;
                    float p = (pos ? es : eas) * (pos ? st_e[kg + e] : st_ea[kg + e]);
                    p = ((m8 >> e) & 1u) ? p : 0.f;
                    __half ph = __float2half_rn(p);
                    lpart += __half2float(ph);
                    w |= (uint32_t)__half_as_ushort(ph) << (16 * sub);
                }
                pk[e2] = w;
            }
            *(uint4*)&sPh[i * 40 + q * 8] = make_uint4(pk[0], pk[1], pk[2], pk[3]);
        }
        // prefetch next
        if (c < 127) {
            mcur = mrow[c + 1];
            bv = *(const uint2*)(hTrow + (c + 1) * 32 + bk);
        }
        __syncthreads();

        // ---- MMA: warp tile 16 x 32, K=32 (2 x k16) ----
        #pragma unroll
        for (int kst = 0; kst < 2; kst++) {
            int kb = kst * 16;
            uint32_t a[4];
            a[0] = *(const uint32_t*)&sPh[(wrow + gid)     * 40 + kb + 2 * tig];
            a[1] = *(const uint32_t*)&sPh[(wrow + gid + 8) * 40 + kb + 2 * tig];
            a[2] = *(const uint32_t*)&sPh[(wrow + gid)     * 40 + kb + 2 * tig + 8];
            a[3] = *(const uint32_t*)&sPh[(wrow + gid + 8) * 40 + kb + 2 * tig + 8];
            #pragma unroll
            for (int nb = 0; nb < 4; nb++) {
                int n = cc * 32 + nb * 8 + gid;
                uint32_t b0 = *(const uint32_t*)&sBh[n * 40 + kb + 2 * tig];
                uint32_t b1 = *(const uint32_t*)&sBh[n * 40 + kb + 2 * tig + 8];
                mma_f16_16n8k16(acc[nb], a, b0, b1);
            }
        }
    }

    // ---- row-sum reduction -> 1/l ----
    __syncthreads();
    sred[tid] = lpart;
    __syncthreads();
    if (tid < 128)
        slinv[tid] = 1.f / (sred[tid * 4] + sred[tid * 4 + 1] +
                            sred[tid * 4 + 2] + sred[tid * 4 + 3]);
    __syncthreads();

    // ---- epilogue ----
    {
        int rlo = wrow + gid, rhi = rlo + 8;
        float invlo = slinv[rlo], invhi = slinv[rhi];
        #pragma unroll
        for (int nb = 0; nb < 4; nb++) {
            int cb = p2h + cc * 32 + nb * 8 + 2 * tig;
            *(float2*)&out[(i0 + rlo) * C_TOT + cb] =
                make_float2(acc[nb][0] * invlo, acc[nb][1] * invlo);
            *(float2*)&out[(i0 + rhi) * C_TOT + cb] =
                make_float2(acc[nb][2] * invhi, acc[nb][3] * invhi);
        }
    }
}

// ---------------- launch ----------------
extern "C" void kernel_launch(void* const* d_in, const int* in_sizes, int n_in,
                              void* d_out, int out_size) {
    const float* x   = (const float*)d_in[0];
    const int*   adj = (const int*)  d_in[1];
    const float* W   = (const float*)d_in[2];
    const float* a   = (const float*)d_in[3];
    float* out = (float*)d_out;

    cudaFuncSetAttribute(aggregate_mma,
                         cudaFuncAttributeMaxDynamicSharedMemorySize, SMEM_AGG);

    pack_adj<<<(N_NODES * N_NODES) / 256, 256>>>(adj);
    transpose_w<<<dim3(IN_F / 32, C_TOT / 32), 256>>>(W);
    gemm_xw_mma<<<dim3(C_TOT / 64, N_NODES / 128), 256>>>(x);
    attn_coef<<<(N_NODES * NHEADS) / 256, 256>>>(a);
    transpose_h<<<dim3(N_NODES / 32, C_TOT / 32), 256>>>();
    aggregate_mma<<<(N_NODES / 128) * NHEADS, 512, SMEM_AGG>>>(out);
}

// round 6
// speedup vs baseline: 3.0789x; 1.1348x over previous
#include <cuda_runtime.h>
#include <cuda_fp16.h>
#include <cstdint>

#define N_NODES 4096
#define IN_F    512
#define NHEADS  4
#define OUT_F   64
#define C_TOT   256
#define ALPHA   0.2f
#define ESHIFT  2.0f

// ---------------- scratch ----------------
__device__ __half   g_hT  [C_TOT * N_NODES];          // [(h*64+f)][j]  fp16
__device__ float    g_WT  [C_TOT * IN_F];             // W transposed [n][k]
__device__ float    g_s   [NHEADS * N_NODES];
__device__ float    g_Es  [NHEADS * N_NODES];         // exp(s-2)
__device__ float    g_Eas [NHEADS * N_NODES];         // exp(a*s-2)
__device__ float    g_t   [NHEADS * N_NODES];
__device__ float    g_Et  [NHEADS * N_NODES];         // exp(t-2)
__device__ float    g_Eat [NHEADS * N_NODES];         // exp(a*t-2)
__device__ uint32_t g_adjbits[N_NODES * (N_NODES / 32)];

// ---------------- helpers ----------------
__device__ __forceinline__ uint32_t f2tf32(float f) {
    uint32_t u;
    asm("cvt.rna.tf32.f32 %0, %1;" : "=r"(u) : "f"(f));
    return u;
}
__device__ __forceinline__ void mma_tf32_16n8k8(float* d, const uint32_t* a,
                                                uint32_t b0, uint32_t b1) {
    asm volatile(
        "mma.sync.aligned.m16n8k8.row.col.f32.tf32.tf32.f32 "
        "{%0,%1,%2,%3}, {%4,%5,%6,%7}, {%8,%9}, {%0,%1,%2,%3};"
        : "+f"(d[0]), "+f"(d[1]), "+f"(d[2]), "+f"(d[3])
        : "r"(a[0]), "r"(a[1]), "r"(a[2]), "r"(a[3]), "r"(b0), "r"(b1));
}
__device__ __forceinline__ void mma_f16_16n8k16(float* d, const uint32_t* a,
                                                uint32_t b0, uint32_t b1) {
    asm volatile(
        "mma.sync.aligned.m16n8k16.row.col.f32.f16.f16.f32 "
        "{%0,%1,%2,%3}, {%4,%5,%6,%7}, {%8,%9}, {%0,%1,%2,%3};"
        : "+f"(d[0]), "+f"(d[1]), "+f"(d[2]), "+f"(d[3])
        : "r"(a[0]), "r"(a[1]), "r"(a[2]), "r"(a[3]), "r"(b0), "r"(b1));
}

// ---------------- kernel 0: transpose W -> g_WT ----------------
__global__ __launch_bounds__(256) void transpose_w(const float* __restrict__ W) {
    __shared__ float t[32][33];
    int kx = blockIdx.x * 32, nx = blockIdx.y * 32;
    int lx = threadIdx.x & 31, ly = threadIdx.x >> 5;
    #pragma unroll
    for (int q = 0; q < 4; q++)
        t[ly + q*8][lx] = W[(kx + ly + q*8) * C_TOT + nx + lx];
    __syncthreads();
    #pragma unroll
    for (int q = 0; q < 4; q++)
        g_WT[(nx + ly + q*8) * IN_F + kx + lx] = t[lx][ly + q*8];
}

// ---------------- kernel 1d: pack adj into bits ----------------
__global__ __launch_bounds__(256) void pack_adj(const int* __restrict__ adj) {
    int g = blockIdx.x * 256 + threadIdx.x;
    int w = g >> 5, lane = g & 31;
    int v = adj[w * 32 + lane];
    uint32_t b = __ballot_sync(0xffffffffu, v > 0);
    if (lane == 0) g_adjbits[w] = b;
}

// ---------------- kernel 1: h = x@W (tf32 HMMA) + fused epilogue -------------
__global__ __launch_bounds__(256) void gemm_xw_mma(const float* __restrict__ x,
                                                   const float* __restrict__ avec) {
    __shared__ uint32_t sA[128 * 36];     // reused as fp16 sT 64x136
    __shared__ uint32_t sB[64 * 36];
    __shared__ float s_a[128];

    int tid = threadIdx.x, wid = tid >> 5, lane = tid & 31;
    int gid = lane >> 2, tig = lane & 3;
    int wrow = wid * 16;
    int n0 = blockIdx.x * 64, m0 = blockIdx.y * 128;
    int head = blockIdx.x;

    if (tid < 128) s_a[tid] = avec[tid];

    float acc[8][4];
    #pragma unroll
    for (int nb = 0; nb < 8; nb++)
        #pragma unroll
        for (int q = 0; q < 4; q++) acc[nb][q] = 0.f;

    int ar = tid >> 1, aks = (tid & 1) * 16;
    int bn = tid >> 2, bks = (tid & 3) * 8;
    const float* aptr = &x[(m0 + ar) * IN_F + aks];
    const float* bptr = &g_WT[(n0 + bn) * IN_F + bks];

    float4 av[4], bv[2];
    #pragma unroll
    for (int e = 0; e < 4; e++) av[e] = *(const float4*)(aptr + 4 * e);
    #pragma unroll
    for (int e = 0; e < 2; e++) bv[e] = *(const float4*)(bptr + 4 * e);

    for (int it = 0; it < 16; it++) {
        __syncthreads();
        #pragma unroll
        for (int e = 0; e < 4; e++) {
            uint4 u = { f2tf32(av[e].x), f2tf32(av[e].y), f2tf32(av[e].z), f2tf32(av[e].w) };
            *(uint4*)&sA[ar * 36 + aks + 4 * e] = u;
        }
        #pragma unroll
        for (int e = 0; e < 2; e++) {
            uint4 u = { f2tf32(bv[e].x), f2tf32(bv[e].y), f2tf32(bv[e].z), f2tf32(bv[e].w) };
            *(uint4*)&sB[bn * 36 + bks + 4 * e] = u;
        }
        if (it < 15) {
            int kk = (it + 1) * 32;
            #pragma unroll
            for (int e = 0; e < 4; e++) av[e] = *(const float4*)(aptr + kk + 4 * e);
            #pragma unroll
            for (int e = 0; e < 2; e++) bv[e] = *(const float4*)(bptr + kk + 4 * e);
        }
        __syncthreads();

        #pragma unroll
        for (int kst = 0; kst < 4; kst++) {
            int k0 = kst * 8;
            uint32_t a[4];
            a[0] = sA[(wrow + gid)     * 36 + k0 + tig];
            a[1] = sA[(wrow + gid + 8) * 36 + k0 + tig];
            a[2] = sA[(wrow + gid)     * 36 + k0 + tig + 4];
            a[3] = sA[(wrow + gid + 8) * 36 + k0 + tig + 4];
            #pragma unroll
            for (int nb = 0; nb < 8; nb++) {
                uint32_t b0 = sB[(nb * 8 + gid) * 36 + k0 + tig];
                uint32_t b1 = sB[(nb * 8 + gid) * 36 + k0 + tig + 4];
                mma_tf32_16n8k8(acc[nb], a, b0, b1);
            }
        }
    }

    // ---- fused epilogue: s,t + exps ----
    {
        float sp0 = 0.f, sp1 = 0.f, tp0 = 0.f, tp1 = 0.f;
        #pragma unroll
        for (int nb = 0; nb < 8; nb++) {
            int cb = nb * 8 + 2 * tig;
            float a0 = s_a[cb],      a1 = s_a[cb + 1];
            float d0 = s_a[64 + cb], d1 = s_a[64 + cb + 1];
            sp0 += acc[nb][0] * a0 + acc[nb][1] * a1;
            sp1 += acc[nb][2] * a0 + acc[nb][3] * a1;
            tp0 += acc[nb][0] * d0 + acc[nb][1] * d1;
            tp1 += acc[nb][2] * d0 + acc[nb][3] * d1;
        }
        #pragma unroll
        for (int o = 1; o < 4; o <<= 1) {
            sp0 += __shfl_xor_sync(0xffffffffu, sp0, o);
            sp1 += __shfl_xor_sync(0xffffffffu, sp1, o);
            tp0 += __shfl_xor_sync(0xffffffffu, tp0, o);
            tp1 += __shfl_xor_sync(0xffffffffu, tp1, o);
        }
        if (tig == 0) {
            int olo = head * N_NODES + m0 + wrow + gid;
            int ohi = olo + 8;
            g_s [olo] = sp0;                         g_s [ohi] = sp1;
            g_Es [olo] = expf(sp0 - ESHIFT);         g_Es [ohi] = expf(sp1 - ESHIFT);
            g_Eas[olo] = expf(ALPHA * sp0 - ESHIFT); g_Eas[ohi] = expf(ALPHA * sp1 - ESHIFT);
            g_t [olo] = tp0;                         g_t [ohi] = tp1;
            g_Et [olo] = expf(tp0 - ESHIFT);         g_Et [ohi] = expf(tp1 - ESHIFT);
            g_Eat[olo] = expf(ALPHA * tp0 - ESHIFT); g_Eat[ohi] = expf(ALPHA * tp1 - ESHIFT);
        }
    }

    // ---- fused epilogue: fp16 transposed write through smem ----
    __syncthreads();                       // sA reads done; safe to reuse
    __half* sT = (__half*)sA;              // [64 f][128 m] stride 136
    {
        int rlo = wrow + gid, rhi = rlo + 8;
        #pragma unroll
        for (int nb = 0; nb < 8; nb++) {
            int cb = nb * 8 + 2 * tig;
            sT[cb * 136 + rlo]       = __float2half_rn(acc[nb][0]);
            sT[(cb + 1) * 136 + rlo] = __float2half_rn(acc[nb][1]);
            sT[cb * 136 + rhi]       = __float2half_rn(acc[nb][2]);
            sT[(cb + 1) * 136 + rhi] = __float2half_rn(acc[nb][3]);
        }
    }
    __syncthreads();
    #pragma unroll
    for (int itr = 0; itr < 4; itr++) {
        int idx = itr * 256 + tid;         // 0..1023
        int f = idx >> 4, seg = idx & 15;
        uint4 v = *(const uint4*)&sT[f * 136 + seg * 8];
        *(uint4*)&g_hT[(n0 + f) * N_NODES + m0 + seg * 8] = v;
    }
}

// ---------------- kernel 2: fp16 HMMA aggregation, 64-j chunks ----------------
#define AG_TT   0u
#define AG_TE   16384u
#define AG_TEA  32768u
#define AG_P    49152u     // 2 x 128x72 halves = 36864 B
#define AG_B    86016u     // 2 x  64x72 halves = 18432 B
#define AG_RED  104448u    // 512 f
#define AG_LI   106496u    // 128 f
#define SMEM_AGG 107008

__global__ __launch_bounds__(512, 1) void aggregate_mma(float* __restrict__ out) {
    extern __shared__ char smem[];
    float*  st_t  = (float*)(smem + AG_TT);
    float*  st_e  = (float*)(smem + AG_TE);
    float*  st_ea = (float*)(smem + AG_TEA);
    __half* sPh   = (__half*)(smem + AG_P);     // + buf*9216
    __half* sBh   = (__half*)(smem + AG_B);     // + buf*4608
    float*  sred  = (float*)(smem + AG_RED);
    float*  slinv = (float*)(smem + AG_LI);

    int tid = threadIdx.x, wid = tid >> 5, lane = tid & 31;
    int gid = lane >> 2, tig = lane & 3;
    int h = blockIdx.x & 3, tile = blockIdx.x >> 2;
    int i0 = tile * 128;
    int p2h = h * 64;

    // preload all j-side factors
    {
        const float4* gt  = (const float4*)&g_t  [h * N_NODES];
        const float4* ge  = (const float4*)&g_Et [h * N_NODES];
        const float4* gea = (const float4*)&g_Eat[h * N_NODES];
        #pragma unroll
        for (int q = 0; q < 2; q++) {
            int idx = tid + q * 512;
            ((float4*)st_t )[idx] = gt [idx];
            ((float4*)st_e )[idx] = ge [idx];
            ((float4*)st_ea)[idx] = gea[idx];
        }
    }

    // build identity: row i, quarter q
    int i = tid >> 2, q = tid & 3;
    float sv  = g_s  [h * N_NODES + i0 + i];
    float es  = g_Es [h * N_NODES + i0 + i];
    float eas = g_Eas[h * N_NODES + i0 + i];
    const uint32_t* mrow = &g_adjbits[(i0 + i) * 128];
    int msh = (q & 1) * 16, mwi = q >> 1;
    float lpart = 0.f;

    // mma identity
    int wrow = (wid >> 1) * 16, cc = wid & 1;
    float acc[4][4];
    #pragma unroll
    for (int nb = 0; nb < 4; nb++)
        #pragma unroll
        for (int e = 0; e < 4; e++) acc[nb][e] = 0.f;

    // B staging
    int bn = tid >> 3, bk = (tid & 7) * 8;
    const __half* hTrow = &g_hT[(p2h + bn) * N_NODES];

    __syncthreads();   // *** preload of st_t/st_e/st_ea must complete (R5 bug) ***

    // ---- build chunk 0 into buf 0 ----
    {
        uint32_t mw = mrow[mwi] >> msh;
        uint4 bv = *(const uint4*)(hTrow + bk);
        *(uint4*)&sBh[bn * 72 + bk] = bv;
        int kg = q * 16;
        uint32_t pk[8];
        #pragma unroll
        for (int e2 = 0; e2 < 8; e2++) {
            uint32_t w = 0;
            #pragma unroll
            for (int sub = 0; sub < 2; sub++) {
                int e = e2 * 2 + sub;
                float tv = st_t[kg + e];
                bool pos = (sv + tv) > 0.f;
                float p = (pos ? es : eas) * (pos ? st_e[kg + e] : st_ea[kg + e]);
                p = ((mw >> e) & 1u) ? p : 0.f;
                __half ph = __float2half_rn(p);
                lpart += __half2float(ph);
                w |= (uint32_t)__half_as_ushort(ph) << (16 * sub);
            }
            pk[e2] = w;
        }
        *(uint4*)&sPh[i * 72 + q * 16]     = make_uint4(pk[0], pk[1], pk[2], pk[3]);
        *(uint4*)&sPh[i * 72 + q * 16 + 8] = make_uint4(pk[4], pk[5], pk[6], pk[7]);
    }
    __syncthreads();

    for (int c = 0; c < 64; c++) {
        int b = c & 1;
        uint32_t mwN = 0; uint4 bvN = make_uint4(0, 0, 0, 0);
        if (c < 63) {
            mwN = mrow[2 * (c + 1) + mwi] >> msh;
            bvN = *(const uint4*)(hTrow + (c + 1) * 64 + bk);
        }

        // ---- MMA chunk c from buf b ----
        {
            const __half* Pb = sPh + b * 9216;
            const __half* Bb = sBh + b * 4608;
            #pragma unroll
            for (int kst = 0; kst < 4; kst++) {
                int kb = kst * 16;
                uint32_t a[4];
                a[0] = *(const uint32_t*)&Pb[(wrow + gid)     * 72 + kb + 2 * tig];
                a[1] = *(const uint32_t*)&Pb[(wrow + gid + 8) * 72 + kb + 2 * tig];
                a[2] = *(const uint32_t*)&Pb[(wrow + gid)     * 72 + kb + 2 * tig + 8];
                a[3] = *(const uint32_t*)&Pb[(wrow + gid + 8) * 72 + kb + 2 * tig + 8];
                #pragma unroll
                for (int nb = 0; nb < 4; nb++) {
                    int n = cc * 32 + nb * 8 + gid;
                    uint32_t b0 = *(const uint32_t*)&Bb[n * 72 + kb + 2 * tig];
                    uint32_t b1 = *(const uint32_t*)&Bb[n * 72 + kb + 2 * tig + 8];
                    mma_f16_16n8k16(acc[nb], a, b0, b1);
                }
            }
        }

        // ---- build chunk c+1 into buf b^1 ----
        if (c < 63) {
            __half* Pd = sPh + (b ^ 1) * 9216;
            __half* Bd = sBh + (b ^ 1) * 4608;
            *(uint4*)&Bd[bn * 72 + bk] = bvN;
            int kg = (c + 1) * 64 + q * 16;
            uint32_t pk[8];
            #pragma unroll
            for (int e2 = 0; e2 < 8; e2++) {
                uint32_t w = 0;
                #pragma unroll
                for (int sub = 0; sub < 2; sub++) {
                    int e = e2 * 2 + sub;
                    float tv = st_t[kg + e];
                    bool pos = (sv + tv) > 0.f;
                    float p = (pos ? es : eas) * (pos ? st_e[kg + e] : st_ea[kg + e]);
                    p = ((mwN >> e) & 1u) ? p : 0.f;
                    __half ph = __float2half_rn(p);
                    lpart += __half2float(ph);
                    w |= (uint32_t)__half_as_ushort(ph) << (16 * sub);
                }
                pk[e2] = w;
            }
            *(uint4*)&Pd[i * 72 + q * 16]     = make_uint4(pk[0], pk[1], pk[2], pk[3]);
            *(uint4*)&Pd[i * 72 + q * 16 + 8] = make_uint4(pk[4], pk[5], pk[6], pk[7]);
        }
        __syncthreads();
    }

    // ---- row-sum reduction -> 1/l ----
    sred[tid] = lpart;
    __syncthreads();
    if (tid < 128)
        slinv[tid] = 1.f / (sred[tid * 4] + sred[tid * 4 + 1] +
                            sred[tid * 4 + 2] + sred[tid * 4 + 3]);
    __syncthreads();

    // ---- epilogue ----
    {
        int rlo = wrow + gid, rhi = rlo + 8;
        float invlo = slinv[rlo], invhi = slinv[rhi];
        #pragma unroll
        for (int nb = 0; nb < 4; nb++) {
            int cb = p2h + cc * 32 + nb * 8 + 2 * tig;
            *(float2*)&out[(i0 + rlo) * C_TOT + cb] =
                make_float2(acc[nb][0] * invlo, acc[nb][1] * invlo);
            *(float2*)&out[(i0 + rhi) * C_TOT + cb] =
                make_float2(acc[nb][2] * invhi, acc[nb][3] * invhi);
        }
    }
}

// ---------------- launch ----------------
extern "C" void kernel_launch(void* const* d_in, const int* in_sizes, int n_in,
                              void* d_out, int out_size) {
    const float* x   = (const float*)d_in[0];
    const int*   adj = (const int*)  d_in[1];
    const float* W   = (const float*)d_in[2];
    const float* a   = (const float*)d_in[3];
    float* out = (float*)d_out;

    cudaFuncSetAttribute(aggregate_mma,
                         cudaFuncAttributeMaxDynamicSharedMemorySize, SMEM_AGG);

    pack_adj<<<(N_NODES * N_NODES) / 256, 256>>>(adj);
    transpose_w<<<dim3(IN_F / 32, C_TOT / 32), 256>>>(W);
    gemm_xw_mma<<<dim3(C_TOT / 64, N_NODES / 128), 256>>>(x, a);
    aggregate_mma<<<(N_NODES / 128) * NHEADS, 512, SMEM_AGG>>>(out);
}

// round 7
// speedup vs baseline: 4.4724x; 1.4526x over previous
#include <cuda_runtime.h>
#include <cuda_fp16.h>
#include <cstdint>

#define N_NODES 4096
#define IN_F    512
#define NHEADS  4
#define OUT_F   64
#define C_TOT   256
#define ALPHA   0.2f
#define ESHIFT  2.0f

// ---------------- scratch ----------------
__device__ __half   g_hT  [C_TOT * N_NODES];      // [(h*64+f)][j]  fp16
__device__ float    g_WT  [C_TOT * IN_F];         // W transposed [n][k]
__device__ float    g_Es  [NHEADS * N_NODES];     // exp(s-2)   (i-side, fp32)
__device__ float    g_Eas [NHEADS * N_NODES];     // exp(a*s-2)
__device__ __half2  g_ee  [NHEADS * N_NODES];     // (exp(t-2), exp(a*t-2)) (j-side)
__device__ uint32_t g_adjbits[N_NODES * (N_NODES / 32)];

// ---------------- helpers ----------------
__device__ __forceinline__ uint32_t smem_u32(const void* p) {
    uint32_t a;
    asm("{ .reg .u64 t; cvta.to.shared.u64 t, %1; cvt.u32.u64 %0, t; }"
        : "=r"(a) : "l"(p));
    return a;
}
__device__ __forceinline__ uint32_t f2tf32(float f) {
    uint32_t u;
    asm("cvt.rna.tf32.f32 %0, %1;" : "=r"(u) : "f"(f));
    return u;
}
__device__ __forceinline__ void mma_tf32_16n8k8(float* d, const uint32_t* a,
                                                uint32_t b0, uint32_t b1) {
    asm volatile(
        "mma.sync.aligned.m16n8k8.row.col.f32.tf32.tf32.f32 "
        "{%0,%1,%2,%3}, {%4,%5,%6,%7}, {%8,%9}, {%0,%1,%2,%3};"
        : "+f"(d[0]), "+f"(d[1]), "+f"(d[2]), "+f"(d[3])
        : "r"(a[0]), "r"(a[1]), "r"(a[2]), "r"(a[3]), "r"(b0), "r"(b1));
}
__device__ __forceinline__ void mma_f16_16n8k16(float* d, const uint32_t* a,
                                                uint32_t b0, uint32_t b1) {
    asm volatile(
        "mma.sync.aligned.m16n8k16.row.col.f32.f16.f16.f32 "
        "{%0,%1,%2,%3}, {%4,%5,%6,%7}, {%8,%9}, {%0,%1,%2,%3};"
        : "+f"(d[0]), "+f"(d[1]), "+f"(d[2]), "+f"(d[3])
        : "r"(a[0]), "r"(a[1]), "r"(a[2]), "r"(a[3]), "r"(b0), "r"(b1));
}
__device__ __forceinline__ void ldmat_x4(uint32_t* r, uint32_t addr) {
    asm volatile("ldmatrix.sync.aligned.m8n8.x4.shared.b16 {%0,%1,%2,%3}, [%4];"
        : "=r"(r[0]), "=r"(r[1]), "=r"(r[2]), "=r"(r[3]) : "r"(addr));
}

// ---------------- kernel 0: transpose W -> g_WT ----------------
__global__ __launch_bounds__(256) void transpose_w(const float* __restrict__ W) {
    __shared__ float t[32][33];
    int kx = blockIdx.x * 32, nx = blockIdx.y * 32;
    int lx = threadIdx.x & 31, ly = threadIdx.x >> 5;
    #pragma unroll
    for (int q = 0; q < 4; q++)
        t[ly + q*8][lx] = W[(kx + ly + q*8) * C_TOT + nx + lx];
    __syncthreads();
    #pragma unroll
    for (int q = 0; q < 4; q++)
        g_WT[(nx + ly + q*8) * IN_F + kx + lx] = t[lx][ly + q*8];
}

// ---------------- kernel 1d: pack adj into bits ----------------
__global__ __launch_bounds__(256) void pack_adj(const int* __restrict__ adj) {
    int g = blockIdx.x * 256 + threadIdx.x;
    int w = g >> 5, lane = g & 31;
    int v = adj[w * 32 + lane];
    uint32_t b = __ballot_sync(0xffffffffu, v > 0);
    if (lane == 0) g_adjbits[w] = b;
}

// ---------------- kernel 1: h = x@W (tf32 HMMA) + fused epilogue -------------
__global__ __launch_bounds__(256) void gemm_xw_mma(const float* __restrict__ x,
                                                   const float* __restrict__ avec) {
    __shared__ uint32_t sA[128 * 36];     // reused as fp16 sT 64x136
    __shared__ uint32_t sB[64 * 36];
    __shared__ float s_a[128];

    int tid = threadIdx.x, wid = tid >> 5, lane = tid & 31;
    int gid = lane >> 2, tig = lane & 3;
    int wrow = wid * 16;
    int n0 = blockIdx.x * 64, m0 = blockIdx.y * 128;
    int head = blockIdx.x;

    if (tid < 128) s_a[tid] = avec[tid];

    float acc[8][4];
    #pragma unroll
    for (int nb = 0; nb < 8; nb++)
        #pragma unroll
        for (int q = 0; q < 4; q++) acc[nb][q] = 0.f;

    int ar = tid >> 1, aks = (tid & 1) * 16;
    int bn = tid >> 2, bks = (tid & 3) * 8;
    const float* aptr = &x[(m0 + ar) * IN_F + aks];
    const float* bptr = &g_WT[(n0 + bn) * IN_F + bks];

    float4 av[4], bv[2];
    #pragma unroll
    for (int e = 0; e < 4; e++) av[e] = *(const float4*)(aptr + 4 * e);
    #pragma unroll
    for (int e = 0; e < 2; e++) bv[e] = *(const float4*)(bptr + 4 * e);

    for (int it = 0; it < 16; it++) {
        __syncthreads();
        #pragma unroll
        for (int e = 0; e < 4; e++) {
            uint4 u = { f2tf32(av[e].x), f2tf32(av[e].y), f2tf32(av[e].z), f2tf32(av[e].w) };
            *(uint4*)&sA[ar * 36 + aks + 4 * e] = u;
        }
        #pragma unroll
        for (int e = 0; e < 2; e++) {
            uint4 u = { f2tf32(bv[e].x), f2tf32(bv[e].y), f2tf32(bv[e].z), f2tf32(bv[e].w) };
            *(uint4*)&sB[bn * 36 + bks + 4 * e] = u;
        }
        if (it < 15) {
            int kk = (it + 1) * 32;
            #pragma unroll
            for (int e = 0; e < 4; e++) av[e] = *(const float4*)(aptr + kk + 4 * e);
            #pragma unroll
            for (int e = 0; e < 2; e++) bv[e] = *(const float4*)(bptr + kk + 4 * e);
        }
        __syncthreads();

        #pragma unroll
        for (int kst = 0; kst < 4; kst++) {
            int k0 = kst * 8;
            uint32_t a[4];
            a[0] = sA[(wrow + gid)     * 36 + k0 + tig];
            a[1] = sA[(wrow + gid + 8) * 36 + k0 + tig];
            a[2] = sA[(wrow + gid)     * 36 + k0 + tig + 4];
            a[3] = sA[(wrow + gid + 8) * 36 + k0 + tig + 4];
            #pragma unroll
            for (int nb = 0; nb < 8; nb++) {
                uint32_t b0 = sB[(nb * 8 + gid) * 36 + k0 + tig];
                uint32_t b1 = sB[(nb * 8 + gid) * 36 + k0 + tig + 4];
                mma_tf32_16n8k8(acc[nb], a, b0, b1);
            }
        }
    }

    // ---- fused epilogue: s,t dots -> exp factor tables ----
    {
        float sp0 = 0.f, sp1 = 0.f, tp0 = 0.f, tp1 = 0.f;
        #pragma unroll
        for (int nb = 0; nb < 8; nb++) {
            int cb = nb * 8 + 2 * tig;
            float a0 = s_a[cb],      a1 = s_a[cb + 1];
            float d0 = s_a[64 + cb], d1 = s_a[64 + cb + 1];
            sp0 += acc[nb][0] * a0 + acc[nb][1] * a1;
            sp1 += acc[nb][2] * a0 + acc[nb][3] * a1;
            tp0 += acc[nb][0] * d0 + acc[nb][1] * d1;
            tp1 += acc[nb][2] * d0 + acc[nb][3] * d1;
        }
        #pragma unroll
        for (int o = 1; o < 4; o <<= 1) {
            sp0 += __shfl_xor_sync(0xffffffffu, sp0, o);
            sp1 += __shfl_xor_sync(0xffffffffu, sp1, o);
            tp0 += __shfl_xor_sync(0xffffffffu, tp0, o);
            tp1 += __shfl_xor_sync(0xffffffffu, tp1, o);
        }
        if (tig == 0) {
            int olo = head * N_NODES + m0 + wrow + gid;
            int ohi = olo + 8;
            g_Es [olo] = expf(sp0 - ESHIFT);         g_Es [ohi] = expf(sp1 - ESHIFT);
            g_Eas[olo] = expf(ALPHA * sp0 - ESHIFT); g_Eas[ohi] = expf(ALPHA * sp1 - ESHIFT);
            g_ee [olo] = __floats2half2_rn(expf(tp0 - ESHIFT), expf(ALPHA * tp0 - ESHIFT));
            g_ee [ohi] = __floats2half2_rn(expf(tp1 - ESHIFT), expf(ALPHA * tp1 - ESHIFT));
        }
    }

    // ---- fused epilogue: fp16 transposed write through smem ----
    __syncthreads();
    __half* sT = (__half*)sA;              // [64 f][128 m] stride 136
    {
        int rlo = wrow + gid, rhi = rlo + 8;
        #pragma unroll
        for (int nb = 0; nb < 8; nb++) {
            int cb = nb * 8 + 2 * tig;
            sT[cb * 136 + rlo]       = __float2half_rn(acc[nb][0]);
            sT[(cb + 1) * 136 + rlo] = __float2half_rn(acc[nb][1]);
            sT[cb * 136 + rhi]       = __float2half_rn(acc[nb][2]);
            sT[(cb + 1) * 136 + rhi] = __float2half_rn(acc[nb][3]);
        }
    }
    __syncthreads();
    #pragma unroll
    for (int itr = 0; itr < 4; itr++) {
        int idx = itr * 256 + tid;
        int f = idx >> 4, seg = idx & 15;
        uint4 v = *(const uint4*)&sT[f * 136 + seg * 8];
        *(uint4*)&g_hT[(n0 + f) * N_NODES + m0 + seg * 8] = v;
    }
}

// ---------------- kernel 2: aggregation v2 -----------------------------------
// 128-j chunks; warps = (8 m-groups) x (2 k-splits); A-frags built in registers
// via p = max(es*Et, eas*Eat); B via smem + ldmatrix; 1 sync per chunk.
#define AGO_EE   0u          // 4096 half2 = 16384 B
#define AGO_B    16384u      // 2 x (64 x 136 halves) = 2 x 17408 B
#define AGO_RED  51200u      // 2 x 128 f = 1024 B
#define AGO_LI   52224u      // 128 f = 512 B
#define SMEM_AGG 52736
#define B_STRIDE 17408u

__global__ __launch_bounds__(512, 1) void aggregate_v2(float* __restrict__ out) {
    extern __shared__ char smem[];
    __half2* st_ee = (__half2*)(smem + AGO_EE);
    float*   sred  = (float*)(smem + AGO_RED);
    float*   slinv = (float*)(smem + AGO_LI);
    float*   sAcc  = (float*)(smem + AGO_B);    // reused after main loop (32 KB < 34 KB)

    int tid = threadIdx.x, wid = tid >> 5, lane = tid & 31;
    int gid = lane >> 2, tig = lane & 3;
    int h = blockIdx.x & 3, i0 = (blockIdx.x >> 2) * 128;
    int mg = wid & 7, ks = wid >> 3;
    int wrow = mg * 16, r0 = wrow + gid, r1 = r0 + 8;

    // stage j-side factor table (all 4096 half2)
    {
        const uint4* src = (const uint4*)&g_ee[h * N_NODES];
        uint4* dst = (uint4*)st_ee;
        dst[tid]       = src[tid];
        dst[tid + 512] = src[tid + 512];
    }
    float es0 = g_Es[h * N_NODES + i0 + r0], eas0 = g_Eas[h * N_NODES + i0 + r0];
    float es1 = g_Es[h * N_NODES + i0 + r1], eas1 = g_Eas[h * N_NODES + i0 + r1];
    const uint32_t* mr0 = &g_adjbits[(i0 + r0) * 128 + 2 * ks];
    const uint32_t* mr1 = &g_adjbits[(i0 + r1) * 128 + 2 * ks];

    float acc[8][4];
    #pragma unroll
    for (int nb = 0; nb < 8; nb++)
        #pragma unroll
        for (int e = 0; e < 4; e++) acc[nb][e] = 0.f;
    float lp0 = 0.f, lp1 = 0.f;

    // B staging ids
    int brow = tid >> 3, bcol = (tid & 7) * 16;
    const __half* hTrow = &g_hT[(h * 64 + brow) * N_NODES];
    uint32_t sb_base = smem_u32(smem + AGO_B);
    int lmrow = (lane & 15) * 136 + (lane >> 4) * 8;   // ldmatrix per-lane row (halves)

    // masks + B for chunk 0
    uint32_t m0A = mr0[0], m0B = mr0[1], m1A = mr1[0], m1B = mr1[1];
    {
        uint4 pv0 = *(const uint4*)(hTrow + bcol);
        uint4 pv1 = *(const uint4*)(hTrow + bcol + 8);
        __half* B0 = (__half*)(smem + AGO_B);
        *(uint4*)&B0[brow * 136 + bcol]     = pv0;
        *(uint4*)&B0[brow * 136 + bcol + 8] = pv1;
    }
    __syncthreads();

    for (int c = 0; c < 32; c++) {
        int b = c & 1;
        // prefetch next chunk's B + masks
        uint4 nv0, nv1; uint32_t n0A = 0, n0B = 0, n1A = 0, n1B = 0;
        if (c < 31) {
            const __half* src = hTrow + (c + 1) * 128;
            nv0 = *(const uint4*)(src + bcol);
            nv1 = *(const uint4*)(src + bcol + 8);
            n0A = mr0[4 * (c + 1)];     n0B = mr0[4 * (c + 1) + 1];
            n1A = mr1[4 * (c + 1)];     n1B = mr1[4 * (c + 1) + 1];
        }

        // ---- build A-fragments in registers ----
        uint32_t afr[4][4];
        int jc = c * 128 + ks * 64;
        #pragma unroll
        for (int kst = 0; kst < 4; kst++) {
            #pragma unroll
            for (int reg = 0; reg < 4; reg++) {
                int koff = kst * 16 + (reg >> 1) * 8 + 2 * tig;   // 0..62 (even)
                uint32_t mw = (reg & 1) ? ((koff & 32) ? m1B : m1A)
                                        : ((koff & 32) ? m0B : m0A);
                int bit = koff & 31;
                float2 f0 = __half22float2(st_ee[jc + koff]);
                float2 f1 = __half22float2(st_ee[jc + koff + 1]);
                float es  = (reg & 1) ? es1 : es0;
                float eas = (reg & 1) ? eas1 : eas0;
                float p0 = fmaxf(es * f0.x, eas * f0.y);
                float p1 = fmaxf(es * f1.x, eas * f1.y);
                p0 = ((mw >> bit) & 1u) ? p0 : 0.f;
                p1 = ((mw >> (bit + 1)) & 1u) ? p1 : 0.f;
                if (reg & 1) lp1 += p0 + p1; else lp0 += p0 + p1;
                __half2 hp = __floats2half2_rn(p0, p1);
                afr[kst][reg] = *(uint32_t*)&hp;
            }
        }

        // ---- MMA from buf b via ldmatrix ----
        {
            uint32_t bufb = sb_base + b * B_STRIDE;
            #pragma unroll
            for (int kst = 0; kst < 4; kst++) {
                int kb = ks * 64 + kst * 16;
                uint32_t br[4][4];
                #pragma unroll
                for (int nbp = 0; nbp < 4; nbp++)
                    ldmat_x4(br[nbp], bufb + 2u * (uint32_t)(nbp * 16 * 136 + kb + lmrow));
                #pragma unroll
                for (int nb = 0; nb < 8; nb++) {
                    int nbp = nb >> 1, hi = nb & 1;
                    mma_f16_16n8k16(acc[nb], afr[kst], br[nbp][hi], br[nbp][2 + hi]);
                }
            }
        }

        // ---- store prefetched chunk into buf b^1 ----
        if (c < 31) {
            __half* Bd = (__half*)(smem + AGO_B + (b ^ 1) * B_STRIDE);
            *(uint4*)&Bd[brow * 136 + bcol]     = nv0;
            *(uint4*)&Bd[brow * 136 + bcol + 8] = nv1;
            m0A = n0A; m0B = n0B; m1A = n1A; m1B = n1B;
        }
        __syncthreads();
    }

    // ---- l reduction (over tig within warp, then over ks via smem) ----
    #pragma unroll
    for (int o = 1; o < 4; o <<= 1) {
        lp0 += __shfl_xor_sync(0xffffffffu, lp0, o);
        lp1 += __shfl_xor_sync(0xffffffffu, lp1, o);
    }
    if (tig == 0) {
        sred[ks * 128 + r0] = lp0;
        sred[ks * 128 + r1] = lp1;
    }
    // ks=1 warps park their accumulators for the k-split reduction
    if (ks == 1) {
        #pragma unroll
        for (int nb = 0; nb < 8; nb++) {
            int cb = nb * 8 + 2 * tig;
            *(float2*)&sAcc[r0 * 66 + cb] = make_float2(acc[nb][0], acc[nb][1]);
            *(float2*)&sAcc[r1 * 66 + cb] = make_float2(acc[nb][2], acc[nb][3]);
        }
    }
    __syncthreads();
    if (tid < 128) slinv[tid] = 1.f / (sred[tid] + sred[128 + tid]);
    __syncthreads();

    // ---- ks=0 warps: combine k-halves, normalize, store ----
    if (ks == 0) {
        float inv0 = slinv[r0], inv1 = slinv[r1];
        #pragma unroll
        for (int nb = 0; nb < 8; nb++) {
            int cb = nb * 8 + 2 * tig;
            float2 o0 = *(const float2*)&sAcc[r0 * 66 + cb];
            float2 o1 = *(const float2*)&sAcc[r1 * 66 + cb];
            float2 v0 = make_float2((acc[nb][0] + o0.x) * inv0, (acc[nb][1] + o0.y) * inv0);
            float2 v1 = make_float2((acc[nb][2] + o1.x) * inv1, (acc[nb][3] + o1.y) * inv1);
            *(float2*)&out[(i0 + r0) * C_TOT + h * 64 + cb] = v0;
            *(float2*)&out[(i0 + r1) * C_TOT + h * 64 + cb] = v1;
        }
    }
}

// ---------------- launch ----------------
extern "C" void kernel_launch(void* const* d_in, const int* in_sizes, int n_in,
                              void* d_out, int out_size) {
    const float* x   = (const float*)d_in[0];
    const int*   adj = (const int*)  d_in[1];
    const float* W   = (const float*)d_in[2];
    const float* a   = (const float*)d_in[3];
    float* out = (float*)d_out;

    cudaFuncSetAttribute(aggregate_v2,
                         cudaFuncAttributeMaxDynamicSharedMemorySize, SMEM_AGG);

    pack_adj<<<(N_NODES * N_NODES) / 256, 256>>>(adj);
    transpose_w<<<dim3(IN_F / 32, C_TOT / 32), 256>>>(W);
    gemm_xw_mma<<<dim3(C_TOT / 64, N_NODES / 128), 256>>>(x, a);
    aggregate_v2<<<(N_NODES / 128) * NHEADS, 512, SMEM_AGG>>>(out);
}

// round 8
// speedup vs baseline: 5.1315x; 1.1474x over previous
#include <cuda_runtime.h>
#include <cuda_fp16.h>
#include <cstdint>

#define N_NODES 4096
#define IN_F    512
#define NHEADS  4
#define OUT_F   64
#define C_TOT   256
#define ALPHA   0.2f
#define ESHIFT  2.0f

// ---------------- scratch ----------------
__device__ __half   g_hT  [C_TOT * N_NODES];      // [(h*64+f)][j]  fp16
__device__ float    g_WT  [C_TOT * IN_F];         // W^T, pre-rounded to tf32
__device__ __half2  g_esh [NHEADS * N_NODES];     // (exp(s-2), exp(a*s-2))  i-side
__device__ __half2  g_ee  [NHEADS * N_NODES];     // (exp(t-2), exp(a*t-2))  j-side
__device__ uint32_t g_adjbits[N_NODES * (N_NODES / 32)];

// ---------------- helpers ----------------
__device__ __forceinline__ uint32_t smem_u32(const void* p) {
    uint32_t a;
    asm("{ .reg .u64 t; cvta.to.shared.u64 t, %1; cvt.u32.u64 %0, t; }"
        : "=r"(a) : "l"(p));
    return a;
}
__device__ __forceinline__ uint32_t f2tf32(float f) {
    uint32_t u;
    asm("cvt.rna.tf32.f32 %0, %1;" : "=r"(u) : "f"(f));
    return u;
}
__device__ __forceinline__ uint32_t hmul2u(uint32_t a, uint32_t b) {
    uint32_t r; asm("mul.f16x2 %0, %1, %2;" : "=r"(r) : "r"(a), "r"(b)); return r;
}
__device__ __forceinline__ uint32_t hmax2u(uint32_t a, uint32_t b) {
    uint32_t r; asm("max.f16x2 %0, %1, %2;" : "=r"(r) : "r"(a), "r"(b)); return r;
}
__device__ __forceinline__ void mma_tf32_16n8k8(float* d, const uint32_t* a,
                                                uint32_t b0, uint32_t b1) {
    asm volatile(
        "mma.sync.aligned.m16n8k8.row.col.f32.tf32.tf32.f32 "
        "{%0,%1,%2,%3}, {%4,%5,%6,%7}, {%8,%9}, {%0,%1,%2,%3};"
        : "+f"(d[0]), "+f"(d[1]), "+f"(d[2]), "+f"(d[3])
        : "r"(a[0]), "r"(a[1]), "r"(a[2]), "r"(a[3]), "r"(b0), "r"(b1));
}
__device__ __forceinline__ void mma_f16_16n8k16(float* d, const uint32_t* a,
                                                uint32_t b0, uint32_t b1) {
    asm volatile(
        "mma.sync.aligned.m16n8k16.row.col.f32.f16.f16.f32 "
        "{%0,%1,%2,%3}, {%4,%5,%6,%7}, {%8,%9}, {%0,%1,%2,%3};"
        : "+f"(d[0]), "+f"(d[1]), "+f"(d[2]), "+f"(d[3])
        : "r"(a[0]), "r"(a[1]), "r"(a[2]), "r"(a[3]), "r"(b0), "r"(b1));
}
__device__ __forceinline__ void ldmat_x4(uint32_t* r, uint32_t addr) {
    asm volatile("ldmatrix.sync.aligned.m8n8.x4.shared.b16 {%0,%1,%2,%3}, [%4];"
        : "=r"(r[0]), "=r"(r[1]), "=r"(r[2]), "=r"(r[3]) : "r"(addr));
}

// ---------------- kernel 0: transpose W -> g_WT (pre-tf32) ----------------
__global__ __launch_bounds__(256) void transpose_w(const float* __restrict__ W) {
    __shared__ float t[32][33];
    int kx = blockIdx.x * 32, nx = blockIdx.y * 32;
    int lx = threadIdx.x & 31, ly = threadIdx.x >> 5;
    #pragma unroll
    for (int q = 0; q < 4; q++)
        t[ly + q*8][lx] = W[(kx + ly + q*8) * C_TOT + nx + lx];
    __syncthreads();
    #pragma unroll
    for (int q = 0; q < 4; q++)
        g_WT[(nx + ly + q*8) * IN_F + kx + lx] =
            __uint_as_float(f2tf32(t[lx][ly + q*8]));
}

// ---------------- kernel 1d: pack adj into bits ----------------
__global__ __launch_bounds__(256) void pack_adj(const int* __restrict__ adj) {
    int g = blockIdx.x * 256 + threadIdx.x;
    int w = g >> 5, lane = g & 31;
    int v = adj[w * 32 + lane];
    uint32_t b = __ballot_sync(0xffffffffu, v > 0);
    if (lane == 0) g_adjbits[w] = b;
}

// ---------------- kernel 1: h = x@W (tf32 HMMA, 512 thr) + fused epilogue ----
__global__ __launch_bounds__(512) void gemm_xw_mma(const float* __restrict__ x,
                                                   const float* __restrict__ avec) {
    __shared__ uint32_t sA[128 * 36];     // reused as fp16 sT 64x136
    __shared__ uint32_t sB[64 * 36];      // reused as s_part
    __shared__ float s_a[128];

    int tid = threadIdx.x, wid = tid >> 5, lane = tid & 31;
    int gid = lane >> 2, tig = lane & 3;
    int mg = wid & 7, nh = wid >> 3;
    int wrow = mg * 16, ncol0 = nh * 32;
    int n0 = blockIdx.x * 64, m0 = blockIdx.y * 128;
    int head = blockIdx.x;

    if (tid < 128) s_a[tid] = avec[tid];

    float acc[4][4];
    #pragma unroll
    for (int nb = 0; nb < 4; nb++)
        #pragma unroll
        for (int q = 0; q < 4; q++) acc[nb][q] = 0.f;

    int ar = tid >> 2, aks = (tid & 3) * 8;     // A: 128 x 32, 8 floats/thread
    int bn = tid >> 3, bks = (tid & 7) * 4;     // B: 64 x 32, 4 floats/thread
    const float* aptr = &x[(m0 + ar) * IN_F + aks];
    const float* bptr = &g_WT[(n0 + bn) * IN_F + bks];

    float4 av[2]; uint4 bv;
    av[0] = *(const float4*)(aptr);
    av[1] = *(const float4*)(aptr + 4);
    bv = *(const uint4*)(bptr);

    for (int it = 0; it < 16; it++) {
        __syncthreads();
        #pragma unroll
        for (int e = 0; e < 2; e++) {
            uint4 u = { f2tf32(av[e].x), f2tf32(av[e].y), f2tf32(av[e].z), f2tf32(av[e].w) };
            *(uint4*)&sA[ar * 36 + aks + 4 * e] = u;
        }
        *(uint4*)&sB[bn * 36 + bks] = bv;       // already tf32
        if (it < 15) {
            int kk = (it + 1) * 32;
            av[0] = *(const float4*)(aptr + kk);
            av[1] = *(const float4*)(aptr + kk + 4);
            bv = *(const uint4*)(bptr + kk);
        }
        __syncthreads();

        #pragma unroll
        for (int kst = 0; kst < 4; kst++) {
            int k0 = kst * 8;
            uint32_t a[4];
            a[0] = sA[(wrow + gid)     * 36 + k0 + tig];
            a[1] = sA[(wrow + gid + 8) * 36 + k0 + tig];
            a[2] = sA[(wrow + gid)     * 36 + k0 + tig + 4];
            a[3] = sA[(wrow + gid + 8) * 36 + k0 + tig + 4];
            #pragma unroll
            for (int nb = 0; nb < 4; nb++) {
                uint32_t b0 = sB[(ncol0 + nb * 8 + gid) * 36 + k0 + tig];
                uint32_t b1 = sB[(ncol0 + nb * 8 + gid) * 36 + k0 + tig + 4];
                mma_tf32_16n8k8(acc[nb], a, b0, b1);
            }
        }
    }

    // ---- partial s,t dots over this warp's 32 cols ----
    float sp0 = 0.f, sp1 = 0.f, tp0 = 0.f, tp1 = 0.f;
    #pragma unroll
    for (int nb = 0; nb < 4; nb++) {
        int cb = ncol0 + nb * 8 + 2 * tig;
        float a0 = s_a[cb],      a1 = s_a[cb + 1];
        float d0 = s_a[64 + cb], d1 = s_a[64 + cb + 1];
        sp0 += acc[nb][0] * a0 + acc[nb][1] * a1;
        sp1 += acc[nb][2] * a0 + acc[nb][3] * a1;
        tp0 += acc[nb][0] * d0 + acc[nb][1] * d1;
        tp1 += acc[nb][2] * d0 + acc[nb][3] * d1;
    }
    #pragma unroll
    for (int o = 1; o < 4; o <<= 1) {
        sp0 += __shfl_xor_sync(0xffffffffu, sp0, o);
        sp1 += __shfl_xor_sync(0xffffffffu, sp1, o);
        tp0 += __shfl_xor_sync(0xffffffffu, tp0, o);
        tp1 += __shfl_xor_sync(0xffffffffu, tp1, o);
    }

    __syncthreads();                     // all MMA smem reads done
    float* s_part = (float*)sB;          // [128][2]
    if (nh == 1 && tig == 0) {
        s_part[(wrow + gid) * 2]         = sp0;
        s_part[(wrow + gid) * 2 + 1]     = tp0;
        s_part[(wrow + gid + 8) * 2]     = sp1;
        s_part[(wrow + gid + 8) * 2 + 1] = tp1;
    }
    // fp16 transposed write of this warp's 16x32 portion into sT
    __half* sT = (__half*)sA;            // [64 f][128 m] stride 136
    {
        int rlo = wrow + gid, rhi = rlo + 8;
        #pragma unroll
        for (int nb = 0; nb < 4; nb++) {
            int cb = ncol0 + nb * 8 + 2 * tig;
            sT[cb * 136 + rlo]       = __float2half_rn(acc[nb][0]);
            sT[(cb + 1) * 136 + rlo] = __float2half_rn(acc[nb][1]);
            sT[cb * 136 + rhi]       = __float2half_rn(acc[nb][2]);
            sT[(cb + 1) * 136 + rhi] = __float2half_rn(acc[nb][3]);
        }
    }
    __syncthreads();

    if (nh == 0 && tig == 0) {
        int r0 = wrow + gid, r1 = r0 + 8;
        float s0 = sp0 + s_part[r0 * 2], t0 = tp0 + s_part[r0 * 2 + 1];
        float s1 = sp1 + s_part[r1 * 2], t1 = tp1 + s_part[r1 * 2 + 1];
        int olo = head * N_NODES + m0 + r0, ohi = head * N_NODES + m0 + r1;
        g_esh[olo] = __floats2half2_rn(expf(s0 - ESHIFT), expf(ALPHA * s0 - ESHIFT));
        g_esh[ohi] = __floats2half2_rn(expf(s1 - ESHIFT), expf(ALPHA * s1 - ESHIFT));
        g_ee [olo] = __floats2half2_rn(expf(t0 - ESHIFT), expf(ALPHA * t0 - ESHIFT));
        g_ee [ohi] = __floats2half2_rn(expf(t1 - ESHIFT), expf(ALPHA * t1 - ESHIFT));
    }
    #pragma unroll
    for (int itr = 0; itr < 2; itr++) {
        int idx = itr * 512 + tid;       // 0..1023
        int f = idx >> 4, seg = idx & 15;
        uint4 v = *(const uint4*)&sT[f * 136 + seg * 8];
        *(uint4*)&g_hT[(n0 + f) * N_NODES + m0 + seg * 8] = v;
    }
}

// ---------------- kernel 2: aggregation v3 -----------------------------------
// fp16x2 build (p = max(es*Et, eas*Eat)), l via ones-MMA, B via ldmatrix.
#define AGO_EE   0u          // 4096 half2 = 16384 B
#define AGO_B    16384u      // 2 x (64 x 136 halves) = 2 x 17408 B
#define AGO_RED  51200u      // 2 x 128 f
#define AGO_LI   52224u      // 128 f
#define SMEM_AGG 52736
#define B_STRIDE 17408u
#define ONESB    0x3C003C00u

__global__ __launch_bounds__(512, 1) void aggregate_v3(float* __restrict__ out) {
    extern __shared__ char smem[];
    const uint32_t* st_ee = (const uint32_t*)(smem + AGO_EE);
    float* sred  = (float*)(smem + AGO_RED);
    float* slinv = (float*)(smem + AGO_LI);
    float* sAcc  = (float*)(smem + AGO_B);      // reused after main loop

    int tid = threadIdx.x, wid = tid >> 5, lane = tid & 31;
    int gid = lane >> 2, tig = lane & 3;
    int h = blockIdx.x & 3, i0 = (blockIdx.x >> 2) * 128;
    int mg = wid & 7, ks = wid >> 3;
    int wrow = mg * 16, r0 = wrow + gid, r1 = r0 + 8;

    // stage j-side factor table
    {
        const uint4* src = (const uint4*)&g_ee[h * N_NODES];
        uint4* dst = (uint4*)(smem + AGO_EE);
        dst[tid]       = src[tid];
        dst[tid + 512] = src[tid + 512];
    }
    uint32_t esh0 = *(const uint32_t*)&g_esh[h * N_NODES + i0 + r0];
    uint32_t esh1 = *(const uint32_t*)&g_esh[h * N_NODES + i0 + r1];
    const uint32_t* mr0 = &g_adjbits[(i0 + r0) * 128 + 2 * ks];
    const uint32_t* mr1 = &g_adjbits[(i0 + r1) * 128 + 2 * ks];

    float acc[8][4], accl[4];
    #pragma unroll
    for (int nb = 0; nb < 8; nb++)
        #pragma unroll
        for (int e = 0; e < 4; e++) acc[nb][e] = 0.f;
    #pragma unroll
    for (int e = 0; e < 4; e++) accl[e] = 0.f;

    // B staging ids
    int brow = tid >> 3, bcol = (tid & 7) * 16;
    const __half* hTrow = &g_hT[(h * 64 + brow) * N_NODES];
    uint32_t sb_base = smem_u32(smem + AGO_B);
    int lmrow = (lane & 15) * 136 + (lane >> 4) * 8;

    uint2 mw0 = *(const uint2*)mr0;     // words for chunk 0 (this ks half)
    uint2 mw1 = *(const uint2*)mr1;
    {
        uint4 pv0 = *(const uint4*)(hTrow + bcol);
        uint4 pv1 = *(const uint4*)(hTrow + bcol + 8);
        __half* B0 = (__half*)(smem + AGO_B);
        *(uint4*)&B0[brow * 136 + bcol]     = pv0;
        *(uint4*)&B0[brow * 136 + bcol + 8] = pv1;
    }
    __syncthreads();

    for (int c = 0; c < 32; c++) {
        int b = c & 1;
        uint4 nv0, nv1; uint2 nm0, nm1;
        if (c < 31) {
            const __half* src = hTrow + (c + 1) * 128;
            nv0 = *(const uint4*)(src + bcol);
            nv1 = *(const uint4*)(src + bcol + 8);
            nm0 = *(const uint2*)(mr0 + 4 * (c + 1));
            nm1 = *(const uint2*)(mr1 + 4 * (c + 1));
        }

        // ---- build A-fragments: p = max(es*Et, eas*Eat), fp16x2 ----
        uint32_t afr[4][4];
        int jc = c * 128 + ks * 64;
        #pragma unroll
        for (int kst = 0; kst < 4; kst++) {
            #pragma unroll
            for (int kp = 0; kp < 2; kp++) {
                int koff = kst * 16 + kp * 8 + 2 * tig;
                uint2 ee2 = *(const uint2*)(st_ee + jc + koff);
                uint32_t w0 = (koff & 32) ? mw0.y : mw0.x;
                uint32_t w1 = (koff & 32) ? mw1.y : mw1.x;
                int bit = koff & 31;
                uint32_t pA = hmul2u(esh0, ee2.x), pB = hmul2u(esh0, ee2.y);
                uint32_t pk = hmax2u(__byte_perm(pA, pB, 0x5410),
                                     __byte_perm(pA, pB, 0x7632));
                uint32_t km = (((w0 >> bit) & 1u) ? 0x0000FFFFu : 0u) |
                              (((w0 >> bit) & 2u) ? 0xFFFF0000u : 0u);
                afr[kst][2 * kp] = pk & km;
                pA = hmul2u(esh1, ee2.x); pB = hmul2u(esh1, ee2.y);
                pk = hmax2u(__byte_perm(pA, pB, 0x5410),
                            __byte_perm(pA, pB, 0x7632));
                km = (((w1 >> bit) & 1u) ? 0x0000FFFFu : 0u) |
                     (((w1 >> bit) & 2u) ? 0xFFFF0000u : 0u);
                afr[kst][2 * kp + 1] = pk & km;
            }
        }

        // ---- MMA from buf b via ldmatrix (+ ones-MMA for row sums) ----
        {
            uint32_t bufb = sb_base + b * B_STRIDE;
            #pragma unroll
            for (int kst = 0; kst < 4; kst++) {
                int kb = ks * 64 + kst * 16;
                uint32_t br[4][4];
                #pragma unroll
                for (int nbp = 0; nbp < 4; nbp++)
                    ldmat_x4(br[nbp], bufb + 2u * (uint32_t)(nbp * 16 * 136 + kb + lmrow));
                #pragma unroll
                for (int nb = 0; nb < 8; nb++) {
                    int nbp = nb >> 1, hi = nb & 1;
                    mma_f16_16n8k16(acc[nb], afr[kst], br[nbp][hi], br[nbp][2 + hi]);
                }
                mma_f16_16n8k16(accl, afr[kst], ONESB, ONESB);
            }
        }

        // ---- store prefetched chunk into buf b^1 ----
        if (c < 31) {
            __half* Bd = (__half*)(smem + AGO_B + (b ^ 1) * B_STRIDE);
            *(uint4*)&Bd[brow * 136 + bcol]     = nv0;
            *(uint4*)&Bd[brow * 136 + bcol + 8] = nv1;
            mw0 = nm0; mw1 = nm1;
        }
        __syncthreads();
    }

    // ---- l: ones-MMA results (all lanes uniform per row) ----
    if (tig == 0) {
        sred[ks * 128 + r0] = accl[0];
        sred[ks * 128 + r1] = accl[2];
    }
    if (ks == 1) {
        #pragma unroll
        for (int nb = 0; nb < 8; nb++) {
            int cb = nb * 8 + 2 * tig;
            *(float2*)&sAcc[r0 * 66 + cb] = make_float2(acc[nb][0], acc[nb][1]);
            *(float2*)&sAcc[r1 * 66 + cb] = make_float2(acc[nb][2], acc[nb][3]);
        }
    }
    __syncthreads();
    if (tid < 128) slinv[tid] = 1.f / (sred[tid] + sred[128 + tid]);
    __syncthreads();

    if (ks == 0) {
        float inv0 = slinv[r0], inv1 = slinv[r1];
        #pragma unroll
        for (int nb = 0; nb < 8; nb++) {
            int cb = nb * 8 + 2 * tig;
            float2 o0 = *(const float2*)&sAcc[r0 * 66 + cb];
            float2 o1 = *(const float2*)&sAcc[r1 * 66 + cb];
            float2 v0 = make_float2((acc[nb][0] + o0.x) * inv0, (acc[nb][1] + o0.y) * inv0);
            float2 v1 = make_float2((acc[nb][2] + o1.x) * inv1, (acc[nb][3] + o1.y) * inv1);
            *(float2*)&out[(i0 + r0) * C_TOT + h * 64 + cb] = v0;
            *(float2*)&out[(i0 + r1) * C_TOT + h * 64 + cb] = v1;
        }
    }
}

// ---------------- launch ----------------
extern "C" void kernel_launch(void* const* d_in, const int* in_sizes, int n_in,
                              void* d_out, int out_size) {
    const float* x   = (const float*)d_in[0];
    const int*   adj = (const int*)  d_in[1];
    const float* W   = (const float*)d_in[2];
    const float* a   = (const float*)d_in[3];
    float* out = (float*)d_out;

    cudaFuncSetAttribute(aggregate_v3,
                         cudaFuncAttributeMaxDynamicSharedMemorySize, SMEM_AGG);

    pack_adj<<<(N_NODES * N_NODES) / 256, 256>>>(adj);
    transpose_w<<<dim3(IN_F / 32, C_TOT / 32), 256>>>(W);
    gemm_xw_mma<<<dim3(C_TOT / 64, N_NODES / 128), 512>>>(x, a);
    aggregate_v3<<<(N_NODES / 128) * NHEADS, 512, SMEM_AGG>>>(out);
}